// round 11
// baseline (speedup 1.0000x reference)
#include <cuda_runtime.h>
#include <cuda_fp16.h>
#include <cuda_bf16.h>
#include <string.h>

#define EPS 1e-6f
#define BATCH 64
#define VMAX 100000

typedef unsigned long long ull;

// Scratch: vertices in (V, batch-pair, 8-half record) layout, fp16.
// Vertex v, batch-pair p (batches 2p, 2p+1) occupies halves
// [v*256 + p*8 .. +8): {x0,y0,z0,pad, x1,y1,z1,pad}. 16B-aligned per (v,p).
__device__ __align__(16) __half g_trans_h[VMAX * 256];

// ---------------------------------------------------------------------------
// f32x2 packed-math helpers (FFMA2 path — PTX-only)
// ---------------------------------------------------------------------------
__device__ __forceinline__ ull f2pack(float lo, float hi) {
    ull d;
    asm("mov.b64 %0, {%1, %2};" : "=l"(d)
        : "r"(__float_as_uint(lo)), "r"(__float_as_uint(hi)));
    return d;
}
__device__ __forceinline__ float2 f2unpack(ull v) {
    unsigned lo, hi;
    asm("mov.b64 {%0, %1}, %2;" : "=r"(lo), "=r"(hi) : "l"(v));
    return make_float2(__uint_as_float(lo), __uint_as_float(hi));
}
__device__ __forceinline__ ull f2mul(ull a, ull b) {
    ull d; asm("mul.rn.f32x2 %0, %1, %2;" : "=l"(d) : "l"(a), "l"(b)); return d;
}
__device__ __forceinline__ ull f2add(ull a, ull b) {
    ull d; asm("add.rn.f32x2 %0, %1, %2;" : "=l"(d) : "l"(a), "l"(b)); return d;
}
__device__ __forceinline__ ull f2fma(ull a, ull b, ull c) {
    ull d; asm("fma.rn.f32x2 %0, %1, %2, %3;" : "=l"(d) : "l"(a), "l"(b), "l"(c)); return d;
}
__device__ __forceinline__ ull f2rsqrt(ull v) {
    float2 f = f2unpack(v);
    float lo, hi;
    asm("rsqrt.approx.f32 %0, %1;" : "=f"(lo) : "f"(f.x));
    asm("rsqrt.approx.f32 %0, %1;" : "=f"(hi) : "f"(f.y));
    return f2pack(lo, hi);
}
__device__ __forceinline__ ull f2rcp(ull v) {
    float2 f = f2unpack(v);
    float lo, hi;
    asm("rcp.approx.f32 %0, %1;" : "=f"(lo) : "f"(f.x));
    asm("rcp.approx.f32 %0, %1;" : "=f"(hi) : "f"(f.y));
    return f2pack(lo, hi);
}

__device__ __forceinline__ __half2 u2h2(unsigned u) {
    __half2 h; memcpy(&h, &u, 4); return h;
}

// Difference of two vertex records (fp16 HSUB2), converted to packed f32x2.
// Records: {x0,y0}, {z0,pad}, {x1,y1}, {z1,pad}.
__device__ __forceinline__ void vdiff(uint4 rp, uint4 r0, ull& X, ull& Y, ull& Z) {
    __half2 dxy0 = __hsub2(u2h2(rp.x), u2h2(r0.x));  // (dx0, dy0)
    __half2 dz0  = __hsub2(u2h2(rp.y), u2h2(r0.y));  // (dz0, -)
    __half2 dxy1 = __hsub2(u2h2(rp.z), u2h2(r0.z));  // (dx1, dy1)
    __half2 dz1  = __hsub2(u2h2(rp.w), u2h2(r0.w));  // (dz1, -)
    X = f2pack(__low2float(dxy0),  __low2float(dxy1));
    Y = f2pack(__high2float(dxy0), __high2float(dxy1));
    Z = f2pack(__low2float(dz0),   __low2float(dz1));
}

// ---------------------------------------------------------------------------
// Transpose (B, V, 3) fp32 -> interleaved fp16 record layout (R5-proven).
// Block 0 additionally zeroes the output (harness poisons with 0xAA).
// ---------------------------------------------------------------------------
__global__ void transpose_kernel(const float* __restrict__ vertices,
                                 float* __restrict__ out, int V, int out_n) {
    __shared__ float tile[BATCH][97];  // [batch][v_local*3+c], pad to 97
    const int v0 = blockIdx.x * 32;
    const int tid = threadIdx.x;

    if (blockIdx.x == 0 && tid < out_n) out[tid] = 0.0f;

    const int lim = 3 * (V - v0);

    #pragma unroll
    for (int i = tid; i < BATCH * 96; i += 256) {
        int b = i / 96;
        int j = i - b * 96;
        float val = 0.0f;
        if (j < lim) val = vertices[(long long)b * (3LL * V) + (long long)v0 * 3 + j];
        tile[b][j] = val;
    }
    __syncthreads();

    uint4* dst = (uint4*)(g_trans_h + (long long)v0 * 256);
    #pragma unroll
    for (int o = tid; o < 1024; o += 256) {
        int v_local = o >> 5;
        int b2 = o & 31;
        if (v0 + v_local < V) {
            int j = v_local * 3;
            float x0 = tile[2 * b2][j],     y0 = tile[2 * b2][j + 1],     z0 = tile[2 * b2][j + 2];
            float x1 = tile[2 * b2 + 1][j], y1 = tile[2 * b2 + 1][j + 1], z1 = tile[2 * b2 + 1][j + 2];
            __half2 h0 = __floats2half2_rn(x0, y0);
            __half2 h1 = __floats2half2_rn(z0, 0.0f);
            __half2 h2 = __floats2half2_rn(x1, y1);
            __half2 h3 = __floats2half2_rn(z1, 0.0f);
            unsigned u0, u1, u2, u3;
            memcpy(&u0, &h0, 4); memcpy(&u1, &h1, 4);
            memcpy(&u2, &h2, 4); memcpy(&u3, &h3, 4);
            dst[o] = make_uint4(u0, u1, u2, u3);
        }
    }
}

// ---------------------------------------------------------------------------
// Packed loss, algebraically restructured (exact algebra vs reference, with
// one guarded approximation u = al2/(al2+EPS) ~= 1):
//   inv = 1/(al2+EPS)
//   cb1.cb2 = b1.b2 - w,  w = ab1*ab2*inv       (error w*EPS*inv <= ~1e-6*w)
//   q_i = bl2e_i*(1+EPS) - ab_i^2*inv   ( = bl2e_i * s_i >= 0 )
//   den = sqrt(q1*q2) + EPS             ( = cbl1*cbl2 + EPS )
// Only 3 MUFU stages (rcp, rsqrt, rcp) per packed pair.
// ---------------------------------------------------------------------------
__device__ __forceinline__ ull loss2(
    ull ax, ull ay, ull az, ull b1x, ull b1y, ull b1z,
    ull b2x, ull b2y, ull b2z, ull acc)
{
    const ull M1   = f2pack(-1.0f, -1.0f);
    const ull EPS2 = f2pack(EPS, EPS);
    const ull OPE2 = f2pack(1.0f + EPS, 1.0f + EPS);
    const ull ONE2 = f2pack(1.0f, 1.0f);

    ull al2 = f2mul(ax, ax); al2 = f2fma(ay, ay, al2); al2 = f2fma(az, az, al2);
    ull inv = f2rcp(f2add(al2, EPS2));          // 1/(al2+EPS)

    // wing 1
    ull bl2e1 = f2mul(b1x, b1x); bl2e1 = f2fma(b1y, b1y, bl2e1);
    bl2e1 = f2fma(b1z, b1z, bl2e1); bl2e1 = f2add(bl2e1, EPS2);
    ull ab1 = f2mul(ax, b1x); ab1 = f2fma(ay, b1y, ab1); ab1 = f2fma(az, b1z, ab1);
    ull m1 = f2mul(f2mul(ab1, ab1), inv);       // ab1^2 * inv
    ull q1 = f2fma(m1, M1, f2mul(bl2e1, OPE2)); // bl2e1*(1+EPS) - m1

    // wing 2
    ull bl2e2 = f2mul(b2x, b2x); bl2e2 = f2fma(b2y, b2y, bl2e2);
    bl2e2 = f2fma(b2z, b2z, bl2e2); bl2e2 = f2add(bl2e2, EPS2);
    ull ab2 = f2mul(ax, b2x); ab2 = f2fma(ay, b2y, ab2); ab2 = f2fma(az, b2z, ab2);
    ull m2 = f2mul(f2mul(ab2, ab2), inv);
    ull q2 = f2fma(m2, M1, f2mul(bl2e2, OPE2));

    // numerator: cb1 . cb2 = b12 - w   (w*u term folded, u ~= 1)
    ull b12 = f2mul(b1x, b2x); b12 = f2fma(b1y, b2y, b12); b12 = f2fma(b1z, b2z, b12);
    ull w = f2mul(f2mul(ab1, ab2), inv);
    ull num = f2fma(w, M1, b12);                // b12 - w

    // denominator: sqrt(q1*q2) + EPS
    ull P = f2mul(q1, q2);
    ull sq = f2mul(P, f2rsqrt(P));
    ull den = f2add(sq, EPS2);

    ull c = f2mul(num, f2rcp(den));
    ull t = f2add(c, ONE2);
    return f2fma(t, t, acc);
}

// ---------------------------------------------------------------------------
// Main kernel: each warp owns a CONTIGUOUS balanced range of edges (index
// loads stream through L1); next iteration's indices prefetched. Lane l owns
// batches (2l, 2l+1); 4 LDG.128 per edge, fully coalesced.
// launch_bounds(256,6): 40-reg ceiling -> 6 blocks/SM -> 48 resident warps.
// ---------------------------------------------------------------------------
__global__ void __launch_bounds__(256, 6)
flatten_loss_kernel(
    const int* __restrict__ v0s, const int* __restrict__ v1s,
    const int* __restrict__ v2s, const int* __restrict__ v3s,
    float* __restrict__ out, int E)
{
    __shared__ float blockAcc[BATCH];
    const int tid = threadIdx.x;
    if (tid < BATCH) blockAcc[tid] = 0.0f;
    __syncthreads();

    const int lane = tid & 31;
    const int wg = (blockIdx.x * blockDim.x + tid) >> 5;
    const int nwarps = (gridDim.x * blockDim.x) >> 5;

    // Balanced contiguous partition of [0, E)
    const int eBeg = (int)((long long)wg * E / nwarps);
    const int eEnd = (int)((long long)(wg + 1) * E / nwarps);

    const uint4* base = (const uint4*)g_trans_h;  // 32 uint4 per vertex
    ull acc = f2pack(0.0f, 0.0f);

    int i0n = 0, i1n = 0, i2n = 0, i3n = 0;
    if (eBeg < eEnd) {
        i0n = v0s[eBeg]; i1n = v1s[eBeg]; i2n = v2s[eBeg]; i3n = v3s[eBeg];
    }

    for (int e = eBeg; e < eEnd; e++) {
        const int i0 = i0n, i1 = i1n, i2 = i2n, i3 = i3n;
        const int en = e + 1;
        if (en < eEnd) {   // prefetch next indices (independent of gathers)
            i0n = v0s[en]; i1n = v1s[en]; i2n = v2s[en]; i3n = v3s[en];
        }

        uint4 r0 = base[(long long)i0 * 32 + lane];
        uint4 r1 = base[(long long)i1 * 32 + lane];
        uint4 r2 = base[(long long)i2 * 32 + lane];
        uint4 r3 = base[(long long)i3 * 32 + lane];

        ull ax, ay, az, b1x, b1y, b1z, b2x, b2y, b2z;
        vdiff(r1, r0, ax, ay, az);
        vdiff(r2, r0, b1x, b1y, b1z);
        vdiff(r3, r0, b2x, b2y, b2z);

        acc = loss2(ax, ay, az, b1x, b1y, b1z, b2x, b2y, b2z, acc);
    }

    float2 a = f2unpack(acc);
    atomicAdd(&blockAcc[2 * lane], a.x);
    atomicAdd(&blockAcc[2 * lane + 1], a.y);
    __syncthreads();

    if (tid < BATCH) {
        atomicAdd(&out[tid], blockAcc[tid]);
    }
}

// ---------------------------------------------------------------------------
// Entry point
// ---------------------------------------------------------------------------
extern "C" void kernel_launch(void* const* d_in, const int* in_sizes, int n_in,
                              void* d_out, int out_size)
{
    const float* vertices = (const float*)d_in[0];
    const int* v0s = (const int*)d_in[1];
    const int* v1s = (const int*)d_in[2];
    const int* v2s = (const int*)d_in[3];
    const int* v3s = (const int*)d_in[4];
    float* out = (float*)d_out;

    const int E = in_sizes[1];
    int V = in_sizes[0] / (BATCH * 3);
    if (V > VMAX) V = VMAX;

    transpose_kernel<<<(V + 31) / 32, 256>>>(vertices, out, V, out_size);
    flatten_loss_kernel<<<1480, 256>>>(v0s, v1s, v2s, v3s, out, E);
}

// round 13
// speedup vs baseline: 1.0207x; 1.0207x over previous
#include <cuda_runtime.h>
#include <cuda_fp16.h>
#include <cuda_bf16.h>
#include <string.h>

#define EPS 1e-6f
#define BATCH 64
#define VMAX 100000

typedef unsigned long long ull;

// Scratch: vertices in (V, batch-pair, 8-half record) layout, fp16.
// Vertex v, batch-pair p (batches 2p, 2p+1) occupies halves
// [v*256 + p*8 .. +8): {x0,y0,z0,pad, x1,y1,z1,pad}. 16B-aligned per (v,p).
// (Resubmission of R12 after broker-side container failure; no kernel change.)
__device__ __align__(16) __half g_trans_h[VMAX * 256];

// ---------------------------------------------------------------------------
// f32x2 packed-math helpers (FFMA2 path — PTX-only)
// ---------------------------------------------------------------------------
__device__ __forceinline__ ull f2pack(float lo, float hi) {
    ull d;
    asm("mov.b64 %0, {%1, %2};" : "=l"(d)
        : "r"(__float_as_uint(lo)), "r"(__float_as_uint(hi)));
    return d;
}
__device__ __forceinline__ float2 f2unpack(ull v) {
    unsigned lo, hi;
    asm("mov.b64 {%0, %1}, %2;" : "=r"(lo), "=r"(hi) : "l"(v));
    return make_float2(__uint_as_float(lo), __uint_as_float(hi));
}
__device__ __forceinline__ ull f2mul(ull a, ull b) {
    ull d; asm("mul.rn.f32x2 %0, %1, %2;" : "=l"(d) : "l"(a), "l"(b)); return d;
}
__device__ __forceinline__ ull f2add(ull a, ull b) {
    ull d; asm("add.rn.f32x2 %0, %1, %2;" : "=l"(d) : "l"(a), "l"(b)); return d;
}
__device__ __forceinline__ ull f2fma(ull a, ull b, ull c) {
    ull d; asm("fma.rn.f32x2 %0, %1, %2, %3;" : "=l"(d) : "l"(a), "l"(b), "l"(c)); return d;
}
__device__ __forceinline__ ull f2rsqrt(ull v) {
    float2 f = f2unpack(v);
    float lo, hi;
    asm("rsqrt.approx.f32 %0, %1;" : "=f"(lo) : "f"(f.x));
    asm("rsqrt.approx.f32 %0, %1;" : "=f"(hi) : "f"(f.y));
    return f2pack(lo, hi);
}
__device__ __forceinline__ ull f2rcp(ull v) {
    float2 f = f2unpack(v);
    float lo, hi;
    asm("rcp.approx.f32 %0, %1;" : "=f"(lo) : "f"(f.x));
    asm("rcp.approx.f32 %0, %1;" : "=f"(hi) : "f"(f.y));
    return f2pack(lo, hi);
}

__device__ __forceinline__ __half2 u2h2(unsigned u) {
    __half2 h; memcpy(&h, &u, 4); return h;
}

// Difference of two vertex records (fp16 HSUB2), converted to packed f32x2.
// Records: {x0,y0}, {z0,pad}, {x1,y1}, {z1,pad}.
__device__ __forceinline__ void vdiff(uint4 rp, uint4 r0, ull& X, ull& Y, ull& Z) {
    __half2 dxy0 = __hsub2(u2h2(rp.x), u2h2(r0.x));  // (dx0, dy0)
    __half2 dz0  = __hsub2(u2h2(rp.y), u2h2(r0.y));  // (dz0, -)
    __half2 dxy1 = __hsub2(u2h2(rp.z), u2h2(r0.z));  // (dx1, dy1)
    __half2 dz1  = __hsub2(u2h2(rp.w), u2h2(r0.w));  // (dz1, -)
    X = f2pack(__low2float(dxy0),  __low2float(dxy1));
    Y = f2pack(__high2float(dxy0), __high2float(dxy1));
    Z = f2pack(__low2float(dz0),   __low2float(dz1));
}

// ---------------------------------------------------------------------------
// Transpose (B, V, 3) fp32 -> interleaved fp16 record layout (R5-proven).
// Block 0 additionally zeroes the output (harness poisons with 0xAA).
// ---------------------------------------------------------------------------
__global__ void transpose_kernel(const float* __restrict__ vertices,
                                 float* __restrict__ out, int V, int out_n) {
    __shared__ float tile[BATCH][97];  // [batch][v_local*3+c], pad to 97
    const int v0 = blockIdx.x * 32;
    const int tid = threadIdx.x;

    if (blockIdx.x == 0 && tid < out_n) out[tid] = 0.0f;

    const int lim = 3 * (V - v0);

    #pragma unroll
    for (int i = tid; i < BATCH * 96; i += 256) {
        int b = i / 96;
        int j = i - b * 96;
        float val = 0.0f;
        if (j < lim) val = vertices[(long long)b * (3LL * V) + (long long)v0 * 3 + j];
        tile[b][j] = val;
    }
    __syncthreads();

    uint4* dst = (uint4*)(g_trans_h + (long long)v0 * 256);
    #pragma unroll
    for (int o = tid; o < 1024; o += 256) {
        int v_local = o >> 5;
        int b2 = o & 31;
        if (v0 + v_local < V) {
            int j = v_local * 3;
            float x0 = tile[2 * b2][j],     y0 = tile[2 * b2][j + 1],     z0 = tile[2 * b2][j + 2];
            float x1 = tile[2 * b2 + 1][j], y1 = tile[2 * b2 + 1][j + 1], z1 = tile[2 * b2 + 1][j + 2];
            __half2 h0 = __floats2half2_rn(x0, y0);
            __half2 h1 = __floats2half2_rn(z0, 0.0f);
            __half2 h2 = __floats2half2_rn(x1, y1);
            __half2 h3 = __floats2half2_rn(z1, 0.0f);
            unsigned u0, u1, u2, u3;
            memcpy(&u0, &h0, 4); memcpy(&u1, &h1, 4);
            memcpy(&u2, &h2, 4); memcpy(&u3, &h3, 4);
            dst[o] = make_uint4(u0, u1, u2, u3);
        }
    }
}

// ---------------------------------------------------------------------------
// Packed loss, negated-reciprocal factoring (33 f2 ops, 3 MUFU stages):
//   inv  = 1/(al2+EPS),  ninv = -inv
//   q_i  = fma(ab_i, ab_i*ninv, fma(bl2_i, 1+EPS, EPS(1+EPS)))
//        = (bl2_i+EPS)(1+EPS) - ab_i^2*inv  = bl2e_i * s_i  >= 0
//   num  = fma(ab1, ab2*ninv, b1.b2) = b1.b2 - ab1*ab2*inv  ( = cb1.cb2 up to
//          the u=al2/(al2+EPS)~=1 fold, validated R11 )
//   den  = sqrt(q1*q2) + EPS  ( = cbl1*cbl2 + EPS )
// ---------------------------------------------------------------------------
__device__ __forceinline__ ull loss2(
    ull ax, ull ay, ull az, ull b1x, ull b1y, ull b1z,
    ull b2x, ull b2y, ull b2z, ull acc)
{
    const ull M1    = f2pack(-1.0f, -1.0f);
    const ull EPS2  = f2pack(EPS, EPS);
    const ull OPE2  = f2pack(1.0f + EPS, 1.0f + EPS);
    const ull EPSP2 = f2pack(EPS * (1.0f + EPS), EPS * (1.0f + EPS));
    const ull ONE2  = f2pack(1.0f, 1.0f);

    ull al2 = f2mul(ax, ax); al2 = f2fma(ay, ay, al2); al2 = f2fma(az, az, al2);
    ull inv  = f2rcp(f2add(al2, EPS2));   // 1/(al2+EPS)
    ull ninv = f2mul(inv, M1);            // -inv

    ull ab1 = f2mul(ax, b1x); ab1 = f2fma(ay, b1y, ab1); ab1 = f2fma(az, b1z, ab1);
    ull ab2 = f2mul(ax, b2x); ab2 = f2fma(ay, b2y, ab2); ab2 = f2fma(az, b2z, ab2);
    ull nab1i = f2mul(ab1, ninv);
    ull nab2i = f2mul(ab2, ninv);

    ull bl21 = f2mul(b1x, b1x); bl21 = f2fma(b1y, b1y, bl21); bl21 = f2fma(b1z, b1z, bl21);
    ull bl22 = f2mul(b2x, b2x); bl22 = f2fma(b2y, b2y, bl22); bl22 = f2fma(b2z, b2z, bl22);

    ull q1 = f2fma(ab1, nab1i, f2fma(bl21, OPE2, EPSP2));
    ull q2 = f2fma(ab2, nab2i, f2fma(bl22, OPE2, EPSP2));

    ull b12 = f2mul(b1x, b2x); b12 = f2fma(b1y, b2y, b12); b12 = f2fma(b1z, b2z, b12);
    ull num = f2fma(ab1, nab2i, b12);     // b1.b2 - ab1*ab2*inv

    ull P   = f2mul(q1, q2);
    ull den = f2add(f2mul(P, f2rsqrt(P)), EPS2);

    ull c = f2mul(num, f2rcp(den));
    ull t = f2add(c, ONE2);
    return f2fma(t, t, acc);
}

// ---------------------------------------------------------------------------
// Main kernel: each warp owns a CONTIGUOUS balanced range of edges (index
// loads stream through L1); next iteration's indices prefetched. Lane l owns
// batches (2l, 2l+1); 4 LDG.128 per edge, fully coalesced.
// launch_bounds(256,6): 40-reg ceiling -> 6 blocks/SM -> 48 resident warps.
// ---------------------------------------------------------------------------
__global__ void __launch_bounds__(256, 6)
flatten_loss_kernel(
    const int* __restrict__ v0s, const int* __restrict__ v1s,
    const int* __restrict__ v2s, const int* __restrict__ v3s,
    float* __restrict__ out, int E)
{
    __shared__ float blockAcc[BATCH];
    const int tid = threadIdx.x;
    if (tid < BATCH) blockAcc[tid] = 0.0f;
    __syncthreads();

    const int lane = tid & 31;
    const int wg = (blockIdx.x * blockDim.x + tid) >> 5;
    const int nwarps = (gridDim.x * blockDim.x) >> 5;

    // Balanced contiguous partition of [0, E)
    const int eBeg = (int)((long long)wg * E / nwarps);
    const int eEnd = (int)((long long)(wg + 1) * E / nwarps);

    const uint4* base = (const uint4*)g_trans_h;  // 32 uint4 per vertex
    ull acc = f2pack(0.0f, 0.0f);

    int i0n = 0, i1n = 0, i2n = 0, i3n = 0;
    if (eBeg < eEnd) {
        i0n = v0s[eBeg]; i1n = v1s[eBeg]; i2n = v2s[eBeg]; i3n = v3s[eBeg];
    }

    for (int e = eBeg; e < eEnd; e++) {
        const int i0 = i0n, i1 = i1n, i2 = i2n, i3 = i3n;
        const int en = e + 1;
        if (en < eEnd) {   // prefetch next indices (independent of gathers)
            i0n = v0s[en]; i1n = v1s[en]; i2n = v2s[en]; i3n = v3s[en];
        }

        uint4 r0 = base[(long long)i0 * 32 + lane];
        uint4 r1 = base[(long long)i1 * 32 + lane];
        uint4 r2 = base[(long long)i2 * 32 + lane];
        uint4 r3 = base[(long long)i3 * 32 + lane];

        ull ax, ay, az, b1x, b1y, b1z, b2x, b2y, b2z;
        vdiff(r1, r0, ax, ay, az);
        vdiff(r2, r0, b1x, b1y, b1z);
        vdiff(r3, r0, b2x, b2y, b2z);

        acc = loss2(ax, ay, az, b1x, b1y, b1z, b2x, b2y, b2z, acc);
    }

    float2 a = f2unpack(acc);
    atomicAdd(&blockAcc[2 * lane], a.x);
    atomicAdd(&blockAcc[2 * lane + 1], a.y);
    __syncthreads();

    if (tid < BATCH) {
        atomicAdd(&out[tid], blockAcc[tid]);
    }
}

// ---------------------------------------------------------------------------
// Entry point
// ---------------------------------------------------------------------------
extern "C" void kernel_launch(void* const* d_in, const int* in_sizes, int n_in,
                              void* d_out, int out_size)
{
    const float* vertices = (const float*)d_in[0];
    const int* v0s = (const int*)d_in[1];
    const int* v1s = (const int*)d_in[2];
    const int* v2s = (const int*)d_in[3];
    const int* v3s = (const int*)d_in[4];
    float* out = (float*)d_out;

    const int E = in_sizes[1];
    int V = in_sizes[0] / (BATCH * 3);
    if (V > VMAX) V = VMAX;

    transpose_kernel<<<(V + 31) / 32, 256>>>(vertices, out, V, out_size);
    flatten_loss_kernel<<<1480, 256>>>(v0s, v1s, v2s, v3s, out, E);
}

// round 15
// speedup vs baseline: 1.0919x; 1.0697x over previous
#include <cuda_runtime.h>
#include <cuda_fp16.h>
#include <cuda_bf16.h>
#include <string.h>

#define EPS 1e-6f
#define BATCH 64
#define VMAX 100000

typedef unsigned long long ull;

// Scratch: vertices in (V, batch-pair, 8-half record) layout, fp16.
// Vertex v, batch-pair p (batches 2p, 2p+1) occupies halves
// [v*256 + p*8 .. +8): {x0,y0,z0,pad, x1,y1,z1,pad}. 16B-aligned per (v,p).
// (Resubmission of R14 after broker-side container failure; kernel unchanged.)
__device__ __align__(16) __half g_trans_h[VMAX * 256];

// ---------------------------------------------------------------------------
// f32x2 packed-math helpers (FFMA2 path — PTX-only)
// ---------------------------------------------------------------------------
__device__ __forceinline__ ull f2pack(float lo, float hi) {
    ull d;
    asm("mov.b64 %0, {%1, %2};" : "=l"(d)
        : "r"(__float_as_uint(lo)), "r"(__float_as_uint(hi)));
    return d;
}
__device__ __forceinline__ float2 f2unpack(ull v) {
    unsigned lo, hi;
    asm("mov.b64 {%0, %1}, %2;" : "=r"(lo), "=r"(hi) : "l"(v));
    return make_float2(__uint_as_float(lo), __uint_as_float(hi));
}
__device__ __forceinline__ ull f2mul(ull a, ull b) {
    ull d; asm("mul.rn.f32x2 %0, %1, %2;" : "=l"(d) : "l"(a), "l"(b)); return d;
}
__device__ __forceinline__ ull f2add(ull a, ull b) {
    ull d; asm("add.rn.f32x2 %0, %1, %2;" : "=l"(d) : "l"(a), "l"(b)); return d;
}
__device__ __forceinline__ ull f2fma(ull a, ull b, ull c) {
    ull d; asm("fma.rn.f32x2 %0, %1, %2, %3;" : "=l"(d) : "l"(a), "l"(b), "l"(c)); return d;
}
__device__ __forceinline__ ull f2rsqrt(ull v) {
    float2 f = f2unpack(v);
    float lo, hi;
    asm("rsqrt.approx.f32 %0, %1;" : "=f"(lo) : "f"(f.x));
    asm("rsqrt.approx.f32 %0, %1;" : "=f"(hi) : "f"(f.y));
    return f2pack(lo, hi);
}

__device__ __forceinline__ __half2 u2h2(unsigned u) {
    __half2 h; memcpy(&h, &u, 4); return h;
}

// Difference of two vertex records (fp16 HSUB2), converted to packed f32x2.
// Records: {x0,y0}, {z0,pad}, {x1,y1}, {z1,pad}.
__device__ __forceinline__ void vdiff(uint4 rp, uint4 r0, ull& X, ull& Y, ull& Z) {
    __half2 dxy0 = __hsub2(u2h2(rp.x), u2h2(r0.x));  // (dx0, dy0)
    __half2 dz0  = __hsub2(u2h2(rp.y), u2h2(r0.y));  // (dz0, -)
    __half2 dxy1 = __hsub2(u2h2(rp.z), u2h2(r0.z));  // (dx1, dy1)
    __half2 dz1  = __hsub2(u2h2(rp.w), u2h2(r0.w));  // (dz1, -)
    X = f2pack(__low2float(dxy0),  __low2float(dxy1));
    Y = f2pack(__high2float(dxy0), __high2float(dxy1));
    Z = f2pack(__low2float(dz0),   __low2float(dz1));
}

// ---------------------------------------------------------------------------
// Transpose (B, V, 3) fp32 -> interleaved fp16 record layout (R5-proven).
// Block 0 additionally zeroes the output (harness poisons with 0xAA).
// ---------------------------------------------------------------------------
__global__ void transpose_kernel(const float* __restrict__ vertices,
                                 float* __restrict__ out, int V, int out_n) {
    __shared__ float tile[BATCH][97];  // [batch][v_local*3+c], pad to 97
    const int v0 = blockIdx.x * 32;
    const int tid = threadIdx.x;

    if (blockIdx.x == 0 && tid < out_n) out[tid] = 0.0f;

    const int lim = 3 * (V - v0);

    #pragma unroll
    for (int i = tid; i < BATCH * 96; i += 256) {
        int b = i / 96;
        int j = i - b * 96;
        float val = 0.0f;
        if (j < lim) val = vertices[(long long)b * (3LL * V) + (long long)v0 * 3 + j];
        tile[b][j] = val;
    }
    __syncthreads();

    uint4* dst = (uint4*)(g_trans_h + (long long)v0 * 256);
    #pragma unroll
    for (int o = tid; o < 1024; o += 256) {
        int v_local = o >> 5;
        int b2 = o & 31;
        if (v0 + v_local < V) {
            int j = v_local * 3;
            float x0 = tile[2 * b2][j],     y0 = tile[2 * b2][j + 1],     z0 = tile[2 * b2][j + 2];
            float x1 = tile[2 * b2 + 1][j], y1 = tile[2 * b2 + 1][j + 1], z1 = tile[2 * b2 + 1][j + 2];
            __half2 h0 = __floats2half2_rn(x0, y0);
            __half2 h1 = __floats2half2_rn(z0, 0.0f);
            __half2 h2 = __floats2half2_rn(x1, y1);
            __half2 h3 = __floats2half2_rn(z1, 0.0f);
            unsigned u0, u1, u2, u3;
            memcpy(&u0, &h0, 4); memcpy(&u1, &h1, 4);
            memcpy(&u2, &h2, 4); memcpy(&u3, &h3, 4);
            dst[o] = make_uint4(u0, u1, u2, u3);
        }
    }
}

// ---------------------------------------------------------------------------
// Packed loss, reciprocal-free (multiply-through by al2e; 30 f2 ops, ONE
// MUFU stage). Exact identity vs the R13 form:
//   al2e = al2 + EPS,  g_i = bl2_i + EPS  (EPS seeded into the dot fmas)
//   r_i  = ab_i^2 - (1+EPS)*g_i*al2e  ( = -al2e*q_i <= -EPS^2 strictly )
//   P    = r1*r2 = (al2e)^2 * q1*q2 >= EPS^4
//   c    = (b12*al2e - ab1*ab2) * rsqrt(P)   ( al2e cancels )
//   t    = 1 + c;  acc += t*t
// Denominator +EPS fold validated R11-R13 (degenerate cases give num=0
// exactly -> term = 1, matching reference).
// ---------------------------------------------------------------------------
__device__ __forceinline__ ull loss2(
    ull ax, ull ay, ull az, ull b1x, ull b1y, ull b1z,
    ull b2x, ull b2y, ull b2z, ull acc)
{
    const ull M1    = f2pack(-1.0f, -1.0f);
    const ull EPS2  = f2pack(EPS, EPS);
    const ull NOPE2 = f2pack(-(1.0f + EPS), -(1.0f + EPS));
    const ull ONE2  = f2pack(1.0f, 1.0f);

    // Independent dot products (EPS folded into the first fma of each norm)
    ull al2e = f2fma(ax, ax, EPS2);
    al2e = f2fma(ay, ay, al2e); al2e = f2fma(az, az, al2e);

    ull g1 = f2fma(b1x, b1x, EPS2);
    g1 = f2fma(b1y, b1y, g1); g1 = f2fma(b1z, b1z, g1);

    ull g2 = f2fma(b2x, b2x, EPS2);
    g2 = f2fma(b2y, b2y, g2); g2 = f2fma(b2z, b2z, g2);

    ull ab1 = f2mul(ax, b1x); ab1 = f2fma(ay, b1y, ab1); ab1 = f2fma(az, b1z, ab1);
    ull ab2 = f2mul(ax, b2x); ab2 = f2fma(ay, b2y, ab2); ab2 = f2fma(az, b2z, ab2);
    ull b12 = f2mul(b1x, b2x); b12 = f2fma(b1y, b2y, b12); b12 = f2fma(b1z, b2z, b12);

    ull nh = f2mul(al2e, NOPE2);               // -(1+EPS)*al2e  (shared)
    ull r1 = f2fma(ab1, ab1, f2mul(g1, nh));   // <= -EPS^2
    ull r2 = f2fma(ab2, ab2, f2mul(g2, nh));
    ull P  = f2mul(r1, r2);                    // >= EPS^4

    ull rs = f2rsqrt(P);                       // single MUFU stage

    ull w   = f2mul(ab1, ab2);
    ull nrs = f2mul(rs, M1);
    ull t   = f2fma(w, nrs, ONE2);             // 1 - ab1*ab2*rs
    ull u   = f2mul(al2e, rs);
    t = f2fma(b12, u, t);                      // + b12*al2e*rs

    return f2fma(t, t, acc);
}

// ---------------------------------------------------------------------------
// Main kernel: each warp owns a CONTIGUOUS balanced range of edges (index
// loads stream through L1); next iteration's indices prefetched. Lane l owns
// batches (2l, 2l+1); 4 LDG.128 per edge, fully coalesced.
// launch_bounds(256,6): 40-reg ceiling -> 6 blocks/SM -> 48 resident warps.
// ---------------------------------------------------------------------------
__global__ void __launch_bounds__(256, 6)
flatten_loss_kernel(
    const int* __restrict__ v0s, const int* __restrict__ v1s,
    const int* __restrict__ v2s, const int* __restrict__ v3s,
    float* __restrict__ out, int E)
{
    __shared__ float blockAcc[BATCH];
    const int tid = threadIdx.x;
    if (tid < BATCH) blockAcc[tid] = 0.0f;
    __syncthreads();

    const int lane = tid & 31;
    const int wg = (blockIdx.x * blockDim.x + tid) >> 5;
    const int nwarps = (gridDim.x * blockDim.x) >> 5;

    // Balanced contiguous partition of [0, E)
    const int eBeg = (int)((long long)wg * E / nwarps);
    const int eEnd = (int)((long long)(wg + 1) * E / nwarps);

    const uint4* base = (const uint4*)g_trans_h;  // 32 uint4 per vertex
    ull acc = f2pack(0.0f, 0.0f);

    int i0n = 0, i1n = 0, i2n = 0, i3n = 0;
    if (eBeg < eEnd) {
        i0n = v0s[eBeg]; i1n = v1s[eBeg]; i2n = v2s[eBeg]; i3n = v3s[eBeg];
    }

    for (int e = eBeg; e < eEnd; e++) {
        const int i0 = i0n, i1 = i1n, i2 = i2n, i3 = i3n;
        const int en = e + 1;
        if (en < eEnd) {   // prefetch next indices (independent of gathers)
            i0n = v0s[en]; i1n = v1s[en]; i2n = v2s[en]; i3n = v3s[en];
        }

        uint4 r0 = base[(long long)i0 * 32 + lane];
        uint4 r1 = base[(long long)i1 * 32 + lane];
        uint4 r2 = base[(long long)i2 * 32 + lane];
        uint4 r3 = base[(long long)i3 * 32 + lane];

        ull ax, ay, az, b1x, b1y, b1z, b2x, b2y, b2z;
        vdiff(r1, r0, ax, ay, az);
        vdiff(r2, r0, b1x, b1y, b1z);
        vdiff(r3, r0, b2x, b2y, b2z);

        acc = loss2(ax, ay, az, b1x, b1y, b1z, b2x, b2y, b2z, acc);
    }

    float2 a = f2unpack(acc);
    atomicAdd(&blockAcc[2 * lane], a.x);
    atomicAdd(&blockAcc[2 * lane + 1], a.y);
    __syncthreads();

    if (tid < BATCH) {
        atomicAdd(&out[tid], blockAcc[tid]);
    }
}

// ---------------------------------------------------------------------------
// Entry point
// ---------------------------------------------------------------------------
extern "C" void kernel_launch(void* const* d_in, const int* in_sizes, int n_in,
                              void* d_out, int out_size)
{
    const float* vertices = (const float*)d_in[0];
    const int* v0s = (const int*)d_in[1];
    const int* v1s = (const int*)d_in[2];
    const int* v2s = (const int*)d_in[3];
    const int* v3s = (const int*)d_in[4];
    float* out = (float*)d_out;

    const int E = in_sizes[1];
    int V = in_sizes[0] / (BATCH * 3);
    if (V > VMAX) V = VMAX;

    transpose_kernel<<<(V + 31) / 32, 256>>>(vertices, out, V, out_size);
    flatten_loss_kernel<<<1480, 256>>>(v0s, v1s, v2s, v3s, out, E);
}

// round 16
// speedup vs baseline: 1.1656x; 1.0675x over previous
#include <cuda_runtime.h>
#include <cuda_fp16.h>
#include <cuda_bf16.h>
#include <string.h>

#define EPS 1e-6f
#define BATCH 64
#define VMAX 100000

typedef unsigned long long ull;

// Scratch: vertices in (V, batch-pair, 8-half record) layout, fp16.
// Vertex v, batch-pair p (batches 2p, 2p+1) occupies halves
// [v*256 + p*8 .. +8): {x0,y0,z0,pad, x1,y1,z1,pad}. 16B-aligned per (v,p).
__device__ __align__(16) __half g_trans_h[VMAX * 256];

// ---------------------------------------------------------------------------
// f32x2 packed-math helpers (FFMA2 path — PTX-only)
// ---------------------------------------------------------------------------
__device__ __forceinline__ ull f2pack(float lo, float hi) {
    ull d;
    asm("mov.b64 %0, {%1, %2};" : "=l"(d)
        : "r"(__float_as_uint(lo)), "r"(__float_as_uint(hi)));
    return d;
}
__device__ __forceinline__ float2 f2unpack(ull v) {
    unsigned lo, hi;
    asm("mov.b64 {%0, %1}, %2;" : "=r"(lo), "=r"(hi) : "l"(v));
    return make_float2(__uint_as_float(lo), __uint_as_float(hi));
}
__device__ __forceinline__ ull f2mul(ull a, ull b) {
    ull d; asm("mul.rn.f32x2 %0, %1, %2;" : "=l"(d) : "l"(a), "l"(b)); return d;
}
__device__ __forceinline__ ull f2fma(ull a, ull b, ull c) {
    ull d; asm("fma.rn.f32x2 %0, %1, %2, %3;" : "=l"(d) : "l"(a), "l"(b), "l"(c)); return d;
}
__device__ __forceinline__ ull f2rsqrt(ull v) {
    float2 f = f2unpack(v);
    float lo, hi;
    asm("rsqrt.approx.f32 %0, %1;" : "=f"(lo) : "f"(f.x));
    asm("rsqrt.approx.f32 %0, %1;" : "=f"(hi) : "f"(f.y));
    return f2pack(lo, hi);
}

__device__ __forceinline__ __half2 u2h2(unsigned u) {
    __half2 h; memcpy(&h, &u, 4); return h;
}

// Difference of two vertex records (fp16 HSUB2), converted to packed f32x2.
// Records: {x0,y0}, {z0,pad}, {x1,y1}, {z1,pad}.
__device__ __forceinline__ void vdiff(uint4 rp, uint4 r0, ull& X, ull& Y, ull& Z) {
    __half2 dxy0 = __hsub2(u2h2(rp.x), u2h2(r0.x));  // (dx0, dy0)
    __half2 dz0  = __hsub2(u2h2(rp.y), u2h2(r0.y));  // (dz0, -)
    __half2 dxy1 = __hsub2(u2h2(rp.z), u2h2(r0.z));  // (dx1, dy1)
    __half2 dz1  = __hsub2(u2h2(rp.w), u2h2(r0.w));  // (dz1, -)
    X = f2pack(__low2float(dxy0),  __low2float(dxy1));
    Y = f2pack(__high2float(dxy0), __high2float(dxy1));
    Z = f2pack(__low2float(dz0),   __low2float(dz1));
}

// ---------------------------------------------------------------------------
// Transpose (B, V, 3) fp32 -> interleaved fp16 record layout (R5-proven).
// Block 0 additionally zeroes the output (harness poisons with 0xAA).
// ---------------------------------------------------------------------------
__global__ void transpose_kernel(const float* __restrict__ vertices,
                                 float* __restrict__ out, int V, int out_n) {
    __shared__ float tile[BATCH][97];  // [batch][v_local*3+c], pad to 97
    const int v0 = blockIdx.x * 32;
    const int tid = threadIdx.x;

    if (blockIdx.x == 0 && tid < out_n) out[tid] = 0.0f;

    const int lim = 3 * (V - v0);

    #pragma unroll
    for (int i = tid; i < BATCH * 96; i += 256) {
        int b = i / 96;
        int j = i - b * 96;
        float val = 0.0f;
        if (j < lim) val = vertices[(long long)b * (3LL * V) + (long long)v0 * 3 + j];
        tile[b][j] = val;
    }
    __syncthreads();

    uint4* dst = (uint4*)(g_trans_h + (long long)v0 * 256);
    #pragma unroll
    for (int o = tid; o < 1024; o += 256) {
        int v_local = o >> 5;
        int b2 = o & 31;
        if (v0 + v_local < V) {
            int j = v_local * 3;
            float x0 = tile[2 * b2][j],     y0 = tile[2 * b2][j + 1],     z0 = tile[2 * b2][j + 2];
            float x1 = tile[2 * b2 + 1][j], y1 = tile[2 * b2 + 1][j + 1], z1 = tile[2 * b2 + 1][j + 2];
            __half2 h0 = __floats2half2_rn(x0, y0);
            __half2 h1 = __floats2half2_rn(z0, 0.0f);
            __half2 h2 = __floats2half2_rn(x1, y1);
            __half2 h3 = __floats2half2_rn(z1, 0.0f);
            unsigned u0, u1, u2, u3;
            memcpy(&u0, &h0, 4); memcpy(&u1, &h1, 4);
            memcpy(&u2, &h2, 4); memcpy(&u3, &h3, 4);
            dst[o] = make_uint4(u0, u1, u2, u3);
        }
    }
}

// ---------------------------------------------------------------------------
// Packed loss, reciprocal-free (R15-proven; 30 f2 ops, ONE MUFU stage):
//   al2e = al2+EPS, g_i = bl2_i+EPS (EPS seeded into the dot fmas)
//   r_i  = ab_i^2 - (1+EPS)*g_i*al2e <= -EPS^2;  P = r1*r2 >= EPS^4
//   t    = 1 - ab1*ab2*rsqrt(P) + b12*al2e*rsqrt(P);  acc += t*t
// ---------------------------------------------------------------------------
__device__ __forceinline__ ull loss2(
    ull ax, ull ay, ull az, ull b1x, ull b1y, ull b1z,
    ull b2x, ull b2y, ull b2z, ull acc)
{
    const ull M1    = f2pack(-1.0f, -1.0f);
    const ull EPS2  = f2pack(EPS, EPS);
    const ull NOPE2 = f2pack(-(1.0f + EPS), -(1.0f + EPS));
    const ull ONE2  = f2pack(1.0f, 1.0f);

    ull al2e = f2fma(ax, ax, EPS2);
    al2e = f2fma(ay, ay, al2e); al2e = f2fma(az, az, al2e);

    ull g1 = f2fma(b1x, b1x, EPS2);
    g1 = f2fma(b1y, b1y, g1); g1 = f2fma(b1z, b1z, g1);

    ull g2 = f2fma(b2x, b2x, EPS2);
    g2 = f2fma(b2y, b2y, g2); g2 = f2fma(b2z, b2z, g2);

    ull ab1 = f2mul(ax, b1x); ab1 = f2fma(ay, b1y, ab1); ab1 = f2fma(az, b1z, ab1);
    ull ab2 = f2mul(ax, b2x); ab2 = f2fma(ay, b2y, ab2); ab2 = f2fma(az, b2z, ab2);
    ull b12 = f2mul(b1x, b2x); b12 = f2fma(b1y, b2y, b12); b12 = f2fma(b1z, b2z, b12);

    ull nh = f2mul(al2e, NOPE2);
    ull r1 = f2fma(ab1, ab1, f2mul(g1, nh));
    ull r2 = f2fma(ab2, ab2, f2mul(g2, nh));
    ull P  = f2mul(r1, r2);

    ull rs = f2rsqrt(P);

    ull w   = f2mul(ab1, ab2);
    ull nrs = f2mul(rs, M1);
    ull t   = f2fma(w, nrs, ONE2);
    ull u   = f2mul(al2e, rs);
    t = f2fma(b12, u, t);

    return f2fma(t, t, acc);
}

// Full per-edge step: gather 4 records, diff, loss.
__device__ __forceinline__ ull edge_math(
    uint4 r0, uint4 r1, uint4 r2, uint4 r3, ull acc)
{
    ull ax, ay, az, b1x, b1y, b1z, b2x, b2y, b2z;
    vdiff(r1, r0, ax, ay, az);
    vdiff(r2, r0, b1x, b1y, b1z);
    vdiff(r3, r0, b2x, b2y, b2z);
    return loss2(ax, ay, az, b1x, b1y, b1z, b2x, b2y, b2z, acc);
}

// ---------------------------------------------------------------------------
// Main kernel: each warp owns a contiguous balanced edge range; TWO edges per
// iteration (8 independent LDG.128 in flight), next pair's indices
// prefetched. Lane l owns batches (2l, 2l+1).
// launch_bounds(256,5): 51-reg ceiling -> 5 blocks/SM -> 40 resident warps.
// ---------------------------------------------------------------------------
__global__ void __launch_bounds__(256, 5)
flatten_loss_kernel(
    const int* __restrict__ v0s, const int* __restrict__ v1s,
    const int* __restrict__ v2s, const int* __restrict__ v3s,
    float* __restrict__ out, int E)
{
    __shared__ float blockAcc[BATCH];
    const int tid = threadIdx.x;
    if (tid < BATCH) blockAcc[tid] = 0.0f;
    __syncthreads();

    const int lane = tid & 31;
    const int wg = (blockIdx.x * blockDim.x + tid) >> 5;
    const int nwarps = (gridDim.x * blockDim.x) >> 5;

    const int eBeg = (int)((long long)wg * E / nwarps);
    const int eEnd = (int)((long long)(wg + 1) * E / nwarps);

    const uint4* base = (const uint4*)g_trans_h;  // 32 uint4 per vertex
    ull acc = f2pack(0.0f, 0.0f);

    int e = eBeg;
    int ia0 = 0, ia1 = 0, ia2 = 0, ia3 = 0;
    int ib0 = 0, ib1 = 0, ib2 = 0, ib3 = 0;
    if (e + 1 < eEnd) {
        ia0 = v0s[e];     ia1 = v1s[e];     ia2 = v2s[e];     ia3 = v3s[e];
        ib0 = v0s[e + 1]; ib1 = v1s[e + 1]; ib2 = v2s[e + 1]; ib3 = v3s[e + 1];
    }

    for (; e + 1 < eEnd; e += 2) {
        // 8 independent gathers for the current pair
        uint4 ra0 = base[(long long)ia0 * 32 + lane];
        uint4 ra1 = base[(long long)ia1 * 32 + lane];
        uint4 ra2 = base[(long long)ia2 * 32 + lane];
        uint4 ra3 = base[(long long)ia3 * 32 + lane];
        uint4 rb0 = base[(long long)ib0 * 32 + lane];
        uint4 rb1 = base[(long long)ib1 * 32 + lane];
        uint4 rb2 = base[(long long)ib2 * 32 + lane];
        uint4 rb3 = base[(long long)ib3 * 32 + lane];

        // prefetch next pair's indices (L1-hit streams)
        if (e + 3 < eEnd) {
            ia0 = v0s[e + 2]; ia1 = v1s[e + 2]; ia2 = v2s[e + 2]; ia3 = v3s[e + 2];
            ib0 = v0s[e + 3]; ib1 = v1s[e + 3]; ib2 = v2s[e + 3]; ib3 = v3s[e + 3];
        }

        acc = edge_math(ra0, ra1, ra2, ra3, acc);
        acc = edge_math(rb0, rb1, rb2, rb3, acc);
    }

    // remainder edge (ranges differ by at most 1 in length parity)
    if (e < eEnd) {
        int i0 = v0s[e], i1 = v1s[e], i2 = v2s[e], i3 = v3s[e];
        uint4 r0 = base[(long long)i0 * 32 + lane];
        uint4 r1 = base[(long long)i1 * 32 + lane];
        uint4 r2 = base[(long long)i2 * 32 + lane];
        uint4 r3 = base[(long long)i3 * 32 + lane];
        acc = edge_math(r0, r1, r2, r3, acc);
    }

    float2 a = f2unpack(acc);
    atomicAdd(&blockAcc[2 * lane], a.x);
    atomicAdd(&blockAcc[2 * lane + 1], a.y);
    __syncthreads();

    if (tid < BATCH) {
        atomicAdd(&out[tid], blockAcc[tid]);
    }
}

// ---------------------------------------------------------------------------
// Entry point
// ---------------------------------------------------------------------------
extern "C" void kernel_launch(void* const* d_in, const int* in_sizes, int n_in,
                              void* d_out, int out_size)
{
    const float* vertices = (const float*)d_in[0];
    const int* v0s = (const int*)d_in[1];
    const int* v1s = (const int*)d_in[2];
    const int* v2s = (const int*)d_in[3];
    const int* v3s = (const int*)d_in[4];
    float* out = (float*)d_out;

    const int E = in_sizes[1];
    int V = in_sizes[0] / (BATCH * 3);
    if (V > VMAX) V = VMAX;

    transpose_kernel<<<(V + 31) / 32, 256>>>(vertices, out, V, out_size);
    flatten_loss_kernel<<<1480, 256>>>(v0s, v1s, v2s, v3s, out, E);
}